// round 1
// baseline (speedup 1.0000x reference)
#include <cuda_runtime.h>
#include <math.h>

#define BATCH 4
#define HEADS 16
#define SEQ   2048
#define DKDIM 64
#define BH    (BATCH*HEADS)

#define TQ 128          // q rows per block tile
#define TK 64           // k cols per block tile (also DK tile)
#define PAD 65          // padded smem row stride (bank-conflict free)

// -------------------------------------------------------------------------
// Kernel 1: scores[b,h,q,k] = mask ? (Q.K^T)*0.125 : -1e9, written into the
// attn region of d_out (used as scratch, later normalized in place).
// Block: 256 threads (16x16), each computes an 8x4 register tile.
// -------------------------------------------------------------------------
__global__ void scores_kernel(const float* __restrict__ Q,
                              const float* __restrict__ K,
                              const int*   __restrict__ mask,
                              float*       __restrict__ attn)
{
    extern __shared__ float sm[];
    float (*Qs)[PAD] = (float (*)[PAD])sm;                 // [TQ][PAD]
    float (*Ks)[PAD] = (float (*)[PAD])(sm + TQ * PAD);    // [TK][PAD]

    const int bh    = blockIdx.z;
    const int b     = bh / HEADS;
    const int qBase = blockIdx.y * TQ;
    const int kBase = blockIdx.x * TK;

    const float* Qp = Q + (size_t)bh * SEQ * DKDIM;
    const float* Kp = K + (size_t)bh * SEQ * DKDIM;

    const int tx = threadIdx.x, ty = threadIdx.y;
    const int tid = ty * 16 + tx;

    // cooperative, coalesced tile loads (DK=64 contiguous floats per row)
    #pragma unroll
    for (int i = tid; i < TQ * DKDIM; i += 256) {
        int r = i >> 6, c = i & 63;
        Qs[r][c] = Qp[(size_t)(qBase + r) * DKDIM + c];
    }
    #pragma unroll
    for (int i = tid; i < TK * DKDIM; i += 256) {
        int r = i >> 6, c = i & 63;
        Ks[r][c] = Kp[(size_t)(kBase + r) * DKDIM + c];
    }
    __syncthreads();

    float acc[8][4];
    #pragma unroll
    for (int r = 0; r < 8; r++)
        #pragma unroll
        for (int c = 0; c < 4; c++) acc[r][c] = 0.0f;

    #pragma unroll 8
    for (int d = 0; d < DKDIM; d++) {
        float a[8], bb[4];
        #pragma unroll
        for (int r = 0; r < 8; r++) a[r] = Qs[ty * 8 + r][d];
        #pragma unroll
        for (int c = 0; c < 4; c++) bb[c] = Ks[tx * 4 + c][d];
        #pragma unroll
        for (int r = 0; r < 8; r++)
            #pragma unroll
            for (int c = 0; c < 4; c++)
                acc[r][c] = fmaf(a[r], bb[c], acc[r][c]);
    }

    const int* mp = mask + (size_t)b  * SEQ * SEQ;
    float*     ap = attn + (size_t)bh * SEQ * SEQ;

    #pragma unroll
    for (int r = 0; r < 8; r++) {
        const int q = qBase + ty * 8 + r;
        const size_t rowoff = (size_t)q * SEQ;
        #pragma unroll
        for (int c = 0; c < 4; c++) {
            const int k = kBase + tx * 4 + c;
            const int m = mp[rowoff + k];
            ap[rowoff + k] = m ? acc[r][c] * 0.125f : -1e9f;
        }
    }
}

// -------------------------------------------------------------------------
// Kernel 2: in-place row softmax over attn (rows of 2048 floats).
// One block (256 threads) per row; float4 IO (2 vecs / thread).
// -------------------------------------------------------------------------
__global__ void softmax_kernel(float* __restrict__ attn)
{
    const size_t row = blockIdx.x;
    float4* p4 = (float4*)(attn + row * (size_t)SEQ);
    const int tid  = threadIdx.x;
    const int lane = tid & 31, wid = tid >> 5;

    float4 v0 = p4[tid];
    float4 v1 = p4[tid + 256];

    float mx = fmaxf(fmaxf(fmaxf(v0.x, v0.y), fmaxf(v0.z, v0.w)),
                     fmaxf(fmaxf(v1.x, v1.y), fmaxf(v1.z, v1.w)));
    #pragma unroll
    for (int o = 16; o; o >>= 1) mx = fmaxf(mx, __shfl_xor_sync(0xffffffffu, mx, o));

    __shared__ float redm[8];
    __shared__ float reds[8];
    if (!lane) redm[wid] = mx;
    __syncthreads();
    mx = redm[0];
    #pragma unroll
    for (int j = 1; j < 8; j++) mx = fmaxf(mx, redm[j]);

    v0.x = __expf(v0.x - mx); v0.y = __expf(v0.y - mx);
    v0.z = __expf(v0.z - mx); v0.w = __expf(v0.w - mx);
    v1.x = __expf(v1.x - mx); v1.y = __expf(v1.y - mx);
    v1.z = __expf(v1.z - mx); v1.w = __expf(v1.w - mx);

    float s = (v0.x + v0.y) + (v0.z + v0.w) + (v1.x + v1.y) + (v1.z + v1.w);
    #pragma unroll
    for (int o = 16; o; o >>= 1) s += __shfl_xor_sync(0xffffffffu, s, o);
    if (!lane) reds[wid] = s;
    __syncthreads();
    s = reds[0];
    #pragma unroll
    for (int j = 1; j < 8; j++) s += reds[j];

    const float inv = 1.0f / s;
    v0.x *= inv; v0.y *= inv; v0.z *= inv; v0.w *= inv;
    v1.x *= inv; v1.y *= inv; v1.z *= inv; v1.w *= inv;

    p4[tid]       = v0;
    p4[tid + 256] = v1;
}

// -------------------------------------------------------------------------
// Kernel 3: out[b,h,q,d] = sum_k attn[b,h,q,k] * V[b,h,k,d]
// Block tile: 128 q-rows x 64 d-cols; loop over k in tiles of 64.
// -------------------------------------------------------------------------
__global__ void out_kernel(const float* __restrict__ attn,
                           const float* __restrict__ V,
                           float*       __restrict__ out)
{
    extern __shared__ float sm[];
    float (*As)[PAD] = (float (*)[PAD])sm;                 // [TQ][PAD]
    float (*Vs)[PAD] = (float (*)[PAD])(sm + TQ * PAD);    // [TK][PAD]

    const int bh    = blockIdx.y;
    const int qBase = blockIdx.x * TQ;

    const float* ap = attn + (size_t)bh * SEQ * SEQ;
    const float* Vp = V    + (size_t)bh * SEQ * DKDIM;

    const int tx = threadIdx.x, ty = threadIdx.y;
    const int tid = ty * 16 + tx;

    float acc[8][4];
    #pragma unroll
    for (int r = 0; r < 8; r++)
        #pragma unroll
        for (int c = 0; c < 4; c++) acc[r][c] = 0.0f;

    for (int kt = 0; kt < SEQ; kt += TK) {
        #pragma unroll
        for (int i = tid; i < TQ * TK; i += 256) {
            int r = i >> 6, c = i & 63;
            As[r][c] = ap[(size_t)(qBase + r) * SEQ + kt + c];
        }
        #pragma unroll
        for (int i = tid; i < TK * DKDIM; i += 256) {
            int r = i >> 6, c = i & 63;
            Vs[r][c] = Vp[(size_t)(kt + r) * DKDIM + c];
        }
        __syncthreads();

        #pragma unroll 8
        for (int k = 0; k < TK; k++) {
            float a[8], bb[4];
            #pragma unroll
            for (int r = 0; r < 8; r++) a[r] = As[ty * 8 + r][k];
            #pragma unroll
            for (int c = 0; c < 4; c++) bb[c] = Vs[k][tx * 4 + c];
            #pragma unroll
            for (int r = 0; r < 8; r++)
                #pragma unroll
                for (int c = 0; c < 4; c++)
                    acc[r][c] = fmaf(a[r], bb[c], acc[r][c]);
        }
        __syncthreads();
    }

    float* op = out + (size_t)bh * SEQ * DKDIM;
    #pragma unroll
    for (int r = 0; r < 8; r++) {
        const int q = qBase + ty * 8 + r;
        #pragma unroll
        for (int c = 0; c < 4; c++)
            op[(size_t)q * DKDIM + tx * 4 + c] = acc[r][c];
    }
}

// -------------------------------------------------------------------------
// Launch: out (B*H*S*DK floats) first, then attn (B*H*S*S floats), matching
// the reference tuple order (out, attn).
// -------------------------------------------------------------------------
extern "C" void kernel_launch(void* const* d_in, const int* in_sizes, int n_in,
                              void* d_out, int out_size)
{
    const float* Q    = (const float*)d_in[0];
    const float* K    = (const float*)d_in[1];
    const float* V    = (const float*)d_in[2];
    const int*   mask = (const int*)  d_in[3];

    float* out  = (float*)d_out;
    float* attn = out + (size_t)BH * SEQ * DKDIM;   // attn region of d_out

    const int smem = (TQ + TK) * PAD * (int)sizeof(float);  // 49,920 B
    cudaFuncSetAttribute(scores_kernel, cudaFuncAttributeMaxDynamicSharedMemorySize, smem);
    cudaFuncSetAttribute(out_kernel,    cudaFuncAttributeMaxDynamicSharedMemorySize, smem);

    dim3 blk(16, 16);
    scores_kernel<<<dim3(SEQ / TK, SEQ / TQ, BH), blk, smem>>>(Q, K, mask, attn);
    softmax_kernel<<<BH * SEQ, 256>>>(attn);
    out_kernel<<<dim3(SEQ / TQ, BH), blk, smem>>>(attn, V, out);
}

// round 2
// speedup vs baseline: 1.8171x; 1.8171x over previous
#include <cuda_runtime.h>
#include <math.h>

#define BATCH 4
#define HEADS 16
#define SEQ   2048
#define DKDIM 64
#define BH    (BATCH*HEADS)

// ---------------------------------------------------------------------------
// Kernel 1: scores = mask ? (Q.K^T)*0.125 : -1e9   (written to attn region)
// 128x128 block tile, 8x8 thread tile, transposed smem + float4 LDS.
// ---------------------------------------------------------------------------
#define S_PAD 132   // row stride (floats) for [64][128] transposed tiles

__global__ __launch_bounds__(256)
void scores_kernel(const float* __restrict__ Q,
                   const float* __restrict__ K,
                   const int*   __restrict__ mask,
                   float*       __restrict__ attn)
{
    extern __shared__ float sm[];
    float (*Qs)[S_PAD] = (float (*)[S_PAD])sm;                    // [64][128+pad]  Qs[d][q]
    float (*Ks)[S_PAD] = (float (*)[S_PAD])(sm + 64 * S_PAD);     // [64][128+pad]  Ks[d][k]

    const int bh    = blockIdx.z;
    const int b     = bh >> 4;              // HEADS = 16
    const int qBase = blockIdx.y * 128;
    const int kBase = blockIdx.x * 128;

    const float* Qp = Q + (size_t)bh * SEQ * DKDIM;
    const float* Kp = K + (size_t)bh * SEQ * DKDIM;

    const int tid = threadIdx.x;
    const int tx  = tid & 15;       // k-group (8 cols)
    const int ty  = tid >> 4;       // q-group (8 rows)

    // Load 128x64 tiles, storing transposed: Xs[d][row]
    #pragma unroll
    for (int i = tid; i < 2048; i += 256) {           // 2048 float4 per tile
        const int r  = i >> 4;                        // row 0..127
        const int c4 = i & 15;                        // float4 col 0..15
        float4 v = *(const float4*)&Qp[(size_t)(qBase + r) * DKDIM + c4 * 4];
        Qs[c4 * 4 + 0][r] = v.x;
        Qs[c4 * 4 + 1][r] = v.y;
        Qs[c4 * 4 + 2][r] = v.z;
        Qs[c4 * 4 + 3][r] = v.w;
    }
    #pragma unroll
    for (int i = tid; i < 2048; i += 256) {
        const int r  = i >> 4;
        const int c4 = i & 15;
        float4 v = *(const float4*)&Kp[(size_t)(kBase + r) * DKDIM + c4 * 4];
        Ks[c4 * 4 + 0][r] = v.x;
        Ks[c4 * 4 + 1][r] = v.y;
        Ks[c4 * 4 + 2][r] = v.z;
        Ks[c4 * 4 + 3][r] = v.w;
    }
    __syncthreads();

    float acc[8][8];
    #pragma unroll
    for (int r = 0; r < 8; r++)
        #pragma unroll
        for (int c = 0; c < 8; c++) acc[r][c] = 0.0f;

    const int qo = ty * 8;
    const int ko = tx * 8;

    #pragma unroll 4
    for (int d = 0; d < DKDIM; d++) {
        float4 a0 = *(const float4*)&Qs[d][qo];
        float4 a1 = *(const float4*)&Qs[d][qo + 4];
        float4 b0 = *(const float4*)&Ks[d][ko];
        float4 b1 = *(const float4*)&Ks[d][ko + 4];
        float a[8] = {a0.x, a0.y, a0.z, a0.w, a1.x, a1.y, a1.z, a1.w};
        float bb[8] = {b0.x, b0.y, b0.z, b0.w, b1.x, b1.y, b1.z, b1.w};
        #pragma unroll
        for (int r = 0; r < 8; r++)
            #pragma unroll
            for (int c = 0; c < 8; c++)
                acc[r][c] = fmaf(a[r], bb[c], acc[r][c]);
    }

    const int*   mp = mask + (size_t)b  * SEQ * SEQ;
    float*       ap = attn + (size_t)bh * SEQ * SEQ;

    #pragma unroll
    for (int r = 0; r < 8; r++) {
        const size_t rowoff = (size_t)(qBase + qo + r) * SEQ + kBase + ko;
        int4 m0 = *(const int4*)&mp[rowoff];
        int4 m1 = *(const int4*)&mp[rowoff + 4];
        float4 w0, w1;
        w0.x = m0.x ? acc[r][0] * 0.125f : -1e9f;
        w0.y = m0.y ? acc[r][1] * 0.125f : -1e9f;
        w0.z = m0.z ? acc[r][2] * 0.125f : -1e9f;
        w0.w = m0.w ? acc[r][3] * 0.125f : -1e9f;
        w1.x = m1.x ? acc[r][4] * 0.125f : -1e9f;
        w1.y = m1.y ? acc[r][5] * 0.125f : -1e9f;
        w1.z = m1.z ? acc[r][6] * 0.125f : -1e9f;
        w1.w = m1.w ? acc[r][7] * 0.125f : -1e9f;
        *(float4*)&ap[rowoff]     = w0;
        *(float4*)&ap[rowoff + 4] = w1;
    }
}

// ---------------------------------------------------------------------------
// Kernel 2: in-place row softmax (rows of 2048 floats)
// ---------------------------------------------------------------------------
__global__ void softmax_kernel(float* __restrict__ attn)
{
    const size_t row = blockIdx.x;
    float4* p4 = (float4*)(attn + row * (size_t)SEQ);
    const int tid  = threadIdx.x;
    const int lane = tid & 31, wid = tid >> 5;

    float4 v0 = p4[tid];
    float4 v1 = p4[tid + 256];

    float mx = fmaxf(fmaxf(fmaxf(v0.x, v0.y), fmaxf(v0.z, v0.w)),
                     fmaxf(fmaxf(v1.x, v1.y), fmaxf(v1.z, v1.w)));
    #pragma unroll
    for (int o = 16; o; o >>= 1) mx = fmaxf(mx, __shfl_xor_sync(0xffffffffu, mx, o));

    __shared__ float redm[8];
    __shared__ float reds[8];
    if (!lane) redm[wid] = mx;
    __syncthreads();
    mx = redm[0];
    #pragma unroll
    for (int j = 1; j < 8; j++) mx = fmaxf(mx, redm[j]);

    v0.x = __expf(v0.x - mx); v0.y = __expf(v0.y - mx);
    v0.z = __expf(v0.z - mx); v0.w = __expf(v0.w - mx);
    v1.x = __expf(v1.x - mx); v1.y = __expf(v1.y - mx);
    v1.z = __expf(v1.z - mx); v1.w = __expf(v1.w - mx);

    float s = (v0.x + v0.y) + (v0.z + v0.w) + (v1.x + v1.y) + (v1.z + v1.w);
    #pragma unroll
    for (int o = 16; o; o >>= 1) s += __shfl_xor_sync(0xffffffffu, s, o);
    if (!lane) reds[wid] = s;
    __syncthreads();
    s = reds[0];
    #pragma unroll
    for (int j = 1; j < 8; j++) s += reds[j];

    const float inv = 1.0f / s;
    v0.x *= inv; v0.y *= inv; v0.z *= inv; v0.w *= inv;
    v1.x *= inv; v1.y *= inv; v1.z *= inv; v1.w *= inv;

    p4[tid]       = v0;
    p4[tid + 256] = v1;
}

// ---------------------------------------------------------------------------
// Kernel 3: out = attn . V    (128 q x 64 d tile, 4x8 thread tile)
// As stored transposed As[k][q] for float4 inner-loop loads.
// ---------------------------------------------------------------------------
#define V_PAD 68    // row stride for Vs[64][64+pad]

__global__ __launch_bounds__(256)
void out_kernel(const float* __restrict__ attn,
                const float* __restrict__ V,
                float*       __restrict__ out)
{
    extern __shared__ float sm[];
    float (*As)[S_PAD] = (float (*)[S_PAD])sm;                    // [64][128+pad]  As[k][q]
    float (*Vs)[V_PAD] = (float (*)[V_PAD])(sm + 64 * S_PAD);     // [64][64+pad]   Vs[k][d]

    const int bh    = blockIdx.y;
    const int qBase = blockIdx.x * 128;

    const float* ap = attn + (size_t)bh * SEQ * SEQ;
    const float* Vp = V    + (size_t)bh * SEQ * DKDIM;

    const int tid = threadIdx.x;
    const int tx  = tid & 7;        // d-group (8 cols)
    const int ty  = tid >> 3;       // q-group (4 rows), 0..31

    float acc[4][8];
    #pragma unroll
    for (int r = 0; r < 4; r++)
        #pragma unroll
        for (int c = 0; c < 8; c++) acc[r][c] = 0.0f;

    const int qo = ty * 4;
    const int dto = tx * 8;

    for (int kt = 0; kt < SEQ; kt += 64) {
        // attn tile 128 q x 64 k -> As[k][q] transposed
        #pragma unroll
        for (int i = tid; i < 2048; i += 256) {      // 2048 float4
            const int r  = i >> 4;                   // q row 0..127
            const int c4 = i & 15;                   // k float4 0..15
            float4 v = *(const float4*)&ap[(size_t)(qBase + r) * SEQ + kt + c4 * 4];
            As[c4 * 4 + 0][r] = v.x;
            As[c4 * 4 + 1][r] = v.y;
            As[c4 * 4 + 2][r] = v.z;
            As[c4 * 4 + 3][r] = v.w;
        }
        // V tile 64 k x 64 d (natural layout)
        #pragma unroll
        for (int i = tid; i < 1024; i += 256) {      // 1024 float4
            const int r  = i >> 4;                   // k row 0..63
            const int c4 = i & 15;
            *(float4*)&Vs[r][c4 * 4] =
                *(const float4*)&Vp[(size_t)(kt + r) * DKDIM + c4 * 4];
        }
        __syncthreads();

        #pragma unroll 8
        for (int k = 0; k < 64; k++) {
            float4 a4 = *(const float4*)&As[k][qo];
            float4 b0 = *(const float4*)&Vs[k][dto];
            float4 b1 = *(const float4*)&Vs[k][dto + 4];
            float a[4]  = {a4.x, a4.y, a4.z, a4.w};
            float bb[8] = {b0.x, b0.y, b0.z, b0.w, b1.x, b1.y, b1.z, b1.w};
            #pragma unroll
            for (int r = 0; r < 4; r++)
                #pragma unroll
                for (int c = 0; c < 8; c++)
                    acc[r][c] = fmaf(a[r], bb[c], acc[r][c]);
        }
        __syncthreads();
    }

    float* op = out + (size_t)bh * SEQ * DKDIM;
    #pragma unroll
    for (int r = 0; r < 4; r++) {
        const size_t rowoff = (size_t)(qBase + qo + r) * DKDIM + dto;
        float4 w0 = {acc[r][0], acc[r][1], acc[r][2], acc[r][3]};
        float4 w1 = {acc[r][4], acc[r][5], acc[r][6], acc[r][7]};
        *(float4*)&op[rowoff]     = w0;
        *(float4*)&op[rowoff + 4] = w1;
    }
}

// ---------------------------------------------------------------------------
extern "C" void kernel_launch(void* const* d_in, const int* in_sizes, int n_in,
                              void* d_out, int out_size)
{
    const float* Q    = (const float*)d_in[0];
    const float* K    = (const float*)d_in[1];
    const float* V    = (const float*)d_in[2];
    const int*   mask = (const int*)  d_in[3];

    float* out  = (float*)d_out;
    float* attn = out + (size_t)BH * SEQ * DKDIM;

    const int smem_s = 2 * 64 * S_PAD * (int)sizeof(float);               // 67,584 B
    const int smem_o = (64 * S_PAD + 64 * V_PAD) * (int)sizeof(float);    // 51,200 B
    cudaFuncSetAttribute(scores_kernel, cudaFuncAttributeMaxDynamicSharedMemorySize, smem_s);
    cudaFuncSetAttribute(out_kernel,    cudaFuncAttributeMaxDynamicSharedMemorySize, smem_o);

    scores_kernel<<<dim3(SEQ / 128, SEQ / 128, BH), 256, smem_s>>>(Q, K, mask, attn);
    softmax_kernel<<<BH * SEQ, 256>>>(attn);
    out_kernel<<<dim3(SEQ / 128, BH), 256, smem_o>>>(attn, V, out);
}

// round 4
// speedup vs baseline: 3.1077x; 1.7102x over previous
#include <cuda_runtime.h>
#include <cuda_bf16.h>
#include <cstdint>
#include <math.h>

#define BATCH 4
#define HEADS 16
#define SEQ   2048
#define DKDIM 64
#define BH    (BATCH*HEADS)

// ---------------------------------------------------------------------------
// Helpers: ldmatrix + mma.sync (sm_80+ ISA, valid on base sm_103 target)
// ---------------------------------------------------------------------------
__device__ __forceinline__ uint32_t smem_u32(const void* p) {
    uint32_t a;
    asm("{ .reg .u64 t; cvta.to.shared.u64 t, %1; cvt.u32.u64 %0, t; }"
        : "=r"(a) : "l"(p));
    return a;
}

__device__ __forceinline__ void ldsm_x4(uint32_t (&r)[4], uint32_t addr) {
    asm volatile("ldmatrix.sync.aligned.m8n8.x4.shared.b16 {%0,%1,%2,%3}, [%4];"
        : "=r"(r[0]), "=r"(r[1]), "=r"(r[2]), "=r"(r[3]) : "r"(addr));
}
__device__ __forceinline__ void ldsm_x4_t(uint32_t (&r)[4], uint32_t addr) {
    asm volatile("ldmatrix.sync.aligned.m8n8.x4.trans.shared.b16 {%0,%1,%2,%3}, [%4];"
        : "=r"(r[0]), "=r"(r[1]), "=r"(r[2]), "=r"(r[3]) : "r"(addr));
}
__device__ __forceinline__ void mma_bf16(float (&c)[4], const uint32_t (&a)[4],
                                         uint32_t b0, uint32_t b1) {
    asm volatile("mma.sync.aligned.m16n8k16.row.col.f32.bf16.bf16.f32 "
        "{%0,%1,%2,%3}, {%4,%5,%6,%7}, {%8,%9}, {%0,%1,%2,%3};"
        : "+f"(c[0]), "+f"(c[1]), "+f"(c[2]), "+f"(c[3])
        : "r"(a[0]), "r"(a[1]), "r"(a[2]), "r"(a[3]), "r"(b0), "r"(b1));
}

#define SW128(b) ((b) ^ (((b) >> 3) & 0x70))

__device__ __forceinline__ void split_bf16(float x, uint16_t& hi, uint16_t& lo) {
    __nv_bfloat16 h = __float2bfloat16(x);
    __nv_bfloat16 l = __float2bfloat16(x - __bfloat162float(h));
    hi = __bfloat16_as_ushort(h);
    lo = __bfloat16_as_ushort(l);
}

// ---------------------------------------------------------------------------
// Kernel 1: scores = mask ? (Q.K^T)*0.125 : -1e9  (split-bf16 mma.sync)
// CTA: 128 q x 128 k tile, K=64, 8 warps (4x2), warp tile 32m x 64n.
// SMEM: Qhi/Qlo/Khi/Klo, each [128 rows x 64 bf16] = 128B rows, SW128.
// ---------------------------------------------------------------------------
#define S_QHI 0
#define S_QLO 16384
#define S_KHI 32768
#define S_KLO 49152
#define S_SMEM_TOTAL 65536

__global__ __launch_bounds__(256)
void scores_tc(const float* __restrict__ Q, const float* __restrict__ K,
               const int* __restrict__ mask, float* __restrict__ attn)
{
    extern __shared__ char smem[];
    const int tid = threadIdx.x, wid = tid >> 5, lane = tid & 31;

    const int bh = blockIdx.z, b = bh >> 4;
    const int qBase = blockIdx.y * 128, kBase = blockIdx.x * 128;

    const float* Qp = Q + (size_t)bh * SEQ * DKDIM;
    const float* Kp = K + (size_t)bh * SEQ * DKDIM;

    // Convert Q tile [128 x 64] fp32 -> hi/lo bf16, SW128 rows of 128B.
    #pragma unroll
    for (int i = tid; i < 4096; i += 256) {
        const int r = i >> 5, c2 = i & 31;
        float2 v = *(const float2*)&Qp[(size_t)(qBase + r) * DKDIM + c2 * 2];
        uint16_t h0, l0, h1, l1;
        split_bf16(v.x, h0, l0); split_bf16(v.y, h1, l1);
        const uint32_t sw = SW128((uint32_t)(r * 128 + c2 * 4));
        *(uint32_t*)(smem + S_QHI + sw) = (uint32_t)h0 | ((uint32_t)h1 << 16);
        *(uint32_t*)(smem + S_QLO + sw) = (uint32_t)l0 | ((uint32_t)l1 << 16);
    }
    #pragma unroll
    for (int i = tid; i < 4096; i += 256) {
        const int r = i >> 5, c2 = i & 31;
        float2 v = *(const float2*)&Kp[(size_t)(kBase + r) * DKDIM + c2 * 2];
        uint16_t h0, l0, h1, l1;
        split_bf16(v.x, h0, l0); split_bf16(v.y, h1, l1);
        const uint32_t sw = SW128((uint32_t)(r * 128 + c2 * 4));
        *(uint32_t*)(smem + S_KHI + sw) = (uint32_t)h0 | ((uint32_t)h1 << 16);
        *(uint32_t*)(smem + S_KLO + sw) = (uint32_t)l0 | ((uint32_t)l1 << 16);
    }
    __syncthreads();

    const int wm = (wid >> 1) * 32;     // warp m offset (4 warps)
    const int wn = (wid & 1) * 64;      // warp n offset (2 warps)

    float acc[2][8][4];
    #pragma unroll
    for (int mi = 0; mi < 2; mi++)
        #pragma unroll
        for (int nj = 0; nj < 8; nj++)
            #pragma unroll
            for (int e = 0; e < 4; e++) acc[mi][nj][e] = 0.0f;

    const uint32_t qhi = smem_u32(smem + S_QHI), qlo = smem_u32(smem + S_QLO);
    const uint32_t khi = smem_u32(smem + S_KHI), klo = smem_u32(smem + S_KLO);

    const int arow = lane & 15;
    const int abyt = (lane >> 4) << 4;

    #pragma unroll
    for (int t = 0; t < 3; t++) {
        const uint32_t ab = (t < 2) ? qhi : qlo;
        const uint32_t bb = (t == 1) ? klo : khi;
        #pragma unroll
        for (int ks = 0; ks < 4; ks++) {
            const int kb = ks * 32;            // byte offset of k16 chunk
            uint32_t a[2][4];
            #pragma unroll
            for (int mi = 0; mi < 2; mi++)
                ldsm_x4(a[mi], ab + SW128((uint32_t)((wm + mi*16 + arow) * 128 + kb + abyt)));
            #pragma unroll
            for (int nj = 0; nj < 4; nj++) {
                uint32_t bf[4];
                ldsm_x4(bf, bb + SW128((uint32_t)((wn + nj*16 + arow) * 128 + kb + abyt)));
                #pragma unroll
                for (int mi = 0; mi < 2; mi++) {
                    mma_bf16(acc[mi][nj*2],     a[mi], bf[0], bf[2]);
                    mma_bf16(acc[mi][nj*2 + 1], a[mi], bf[1], bf[3]);
                }
            }
        }
    }

    // Epilogue: fused mask + scale, direct stores (float2 per fragment row).
    const int*   mp = mask + (size_t)b  * SEQ * SEQ;
    float*       ap = attn + (size_t)bh * SEQ * SEQ;
    #pragma unroll
    for (int mi = 0; mi < 2; mi++) {
        const int r0 = qBase + wm + mi * 16 + (lane >> 2);
        #pragma unroll
        for (int nj = 0; nj < 8; nj++) {
            const int col = kBase + wn + nj * 8 + (lane & 3) * 2;
            const size_t o0 = (size_t)r0 * SEQ + col;
            const size_t o1 = (size_t)(r0 + 8) * SEQ + col;
            int2 m0 = *(const int2*)&mp[o0];
            int2 m1 = *(const int2*)&mp[o1];
            float2 w0, w1;
            w0.x = m0.x ? acc[mi][nj][0] * 0.125f : -1e9f;
            w0.y = m0.y ? acc[mi][nj][1] * 0.125f : -1e9f;
            w1.x = m1.x ? acc[mi][nj][2] * 0.125f : -1e9f;
            w1.y = m1.y ? acc[mi][nj][3] * 0.125f : -1e9f;
            *(float2*)&ap[o0] = w0;
            *(float2*)&ap[o1] = w1;
        }
    }
}

// ---------------------------------------------------------------------------
// Kernel 2: in-place row softmax (rows of 2048 floats)
// ---------------------------------------------------------------------------
__global__ void softmax_kernel(float* __restrict__ attn)
{
    const size_t row = blockIdx.x;
    float4* p4 = (float4*)(attn + row * (size_t)SEQ);
    const int tid = threadIdx.x;
    const int lane = tid & 31, wid = tid >> 5;

    float4 v0 = p4[tid];
    float4 v1 = p4[tid + 256];

    float mx = fmaxf(fmaxf(fmaxf(v0.x, v0.y), fmaxf(v0.z, v0.w)),
                     fmaxf(fmaxf(v1.x, v1.y), fmaxf(v1.z, v1.w)));
    #pragma unroll
    for (int o = 16; o; o >>= 1) mx = fmaxf(mx, __shfl_xor_sync(0xffffffffu, mx, o));

    __shared__ float redm[8];
    __shared__ float reds[8];
    if (!lane) redm[wid] = mx;
    __syncthreads();
    mx = redm[0];
    #pragma unroll
    for (int j = 1; j < 8; j++) mx = fmaxf(mx, redm[j]);

    v0.x = __expf(v0.x - mx); v0.y = __expf(v0.y - mx);
    v0.z = __expf(v0.z - mx); v0.w = __expf(v0.w - mx);
    v1.x = __expf(v1.x - mx); v1.y = __expf(v1.y - mx);
    v1.z = __expf(v1.z - mx); v1.w = __expf(v1.w - mx);

    float s = (v0.x + v0.y) + (v0.z + v0.w) + (v1.x + v1.y) + (v1.z + v1.w);
    #pragma unroll
    for (int o = 16; o; o >>= 1) s += __shfl_xor_sync(0xffffffffu, s, o);
    if (!lane) reds[wid] = s;
    __syncthreads();
    s = reds[0];
    #pragma unroll
    for (int j = 1; j < 8; j++) s += reds[j];

    const float inv = 1.0f / s;
    v0.x *= inv; v0.y *= inv; v0.z *= inv; v0.w *= inv;
    v1.x *= inv; v1.y *= inv; v1.z *= inv; v1.w *= inv;

    p4[tid]       = v0;
    p4[tid + 256] = v1;
}

// ---------------------------------------------------------------------------
// Kernel 3: out = attn . V  (split-bf16 mma.sync)
// CTA: 128 q x 64 d, K=2048 in 64-wide smem stages. Warp tile 32m x 32n.
// A (attn) row-major [128 x 64], ldmatrix. B = V [64 k x 64 d] natural rows,
// consumed via ldmatrix.trans (k-major -> col-major fragment).
// ---------------------------------------------------------------------------
#define O_AHI 0
#define O_ALO 16384
#define O_BHI 32768
#define O_BLO 40960
#define O_SMEM_TOTAL 49152

__global__ __launch_bounds__(256)
void out_tc(const float* __restrict__ attn, const float* __restrict__ V,
            float* __restrict__ out)
{
    extern __shared__ char smem[];
    const int tid = threadIdx.x, wid = tid >> 5, lane = tid & 31;

    const int bh = blockIdx.y;
    const int qBase = blockIdx.x * 128;

    const float* ap = attn + (size_t)bh * SEQ * SEQ;
    const float* Vp = V    + (size_t)bh * SEQ * DKDIM;

    const int wm = (wid >> 1) * 32;
    const int wn = (wid & 1) * 32;

    float acc[2][4][4];
    #pragma unroll
    for (int mi = 0; mi < 2; mi++)
        #pragma unroll
        for (int nj = 0; nj < 4; nj++)
            #pragma unroll
            for (int e = 0; e < 4; e++) acc[mi][nj][e] = 0.0f;

    const uint32_t ahi = smem_u32(smem + O_AHI), alo = smem_u32(smem + O_ALO);
    const uint32_t bhi = smem_u32(smem + O_BHI), blo = smem_u32(smem + O_BLO);

    const int arow = lane & 15;
    const int abyt = (lane >> 4) << 4;

    for (int kt = 0; kt < SEQ; kt += 64) {
        // A tile: attn[128 q x 64 k] -> hi/lo bf16 SW128 (rows = q, 128B)
        #pragma unroll
        for (int i = tid; i < 4096; i += 256) {
            const int r = i >> 5, c2 = i & 31;
            float2 v = *(const float2*)&ap[(size_t)(qBase + r) * SEQ + kt + c2 * 2];
            uint16_t h0, l0, h1, l1;
            split_bf16(v.x, h0, l0); split_bf16(v.y, h1, l1);
            const uint32_t sw = SW128((uint32_t)(r * 128 + c2 * 4));
            *(uint32_t*)(smem + O_AHI + sw) = (uint32_t)h0 | ((uint32_t)h1 << 16);
            *(uint32_t*)(smem + O_ALO + sw) = (uint32_t)l0 | ((uint32_t)l1 << 16);
        }
        // B tile: V[64 k x 64 d] natural layout (rows = k, 128B), coalesced.
        #pragma unroll
        for (int i = tid; i < 2048; i += 256) {
            const int k = i >> 5, d2 = i & 31;
            float2 v = *(const float2*)&Vp[(size_t)(kt + k) * DKDIM + d2 * 2];
            uint16_t h0, l0, h1, l1;
            split_bf16(v.x, h0, l0); split_bf16(v.y, h1, l1);
            const uint32_t sw = SW128((uint32_t)(k * 128 + d2 * 4));
            *(uint32_t*)(smem + O_BHI + sw) = (uint32_t)h0 | ((uint32_t)h1 << 16);
            *(uint32_t*)(smem + O_BLO + sw) = (uint32_t)l0 | ((uint32_t)l1 << 16);
        }
        __syncthreads();

        #pragma unroll
        for (int t = 0; t < 3; t++) {
            const uint32_t ab = (t < 2) ? ahi : alo;
            const uint32_t bb = (t == 1) ? blo : bhi;
            #pragma unroll
            for (int ks = 0; ks < 4; ks++) {
                uint32_t a[2][4];
                #pragma unroll
                for (int mi = 0; mi < 2; mi++)
                    ldsm_x4(a[mi], ab + SW128((uint32_t)((wm + mi*16 + arow) * 128 + ks*32 + abyt)));
                #pragma unroll
                for (int nj = 0; nj < 2; nj++) {
                    // trans: rows = k (8 rows per tile), byte col = n*2
                    uint32_t bf[4];
                    ldsm_x4_t(bf, bb + SW128((uint32_t)((ks*16 + arow) * 128 + (wn + nj*16)*2 + abyt)));
                    #pragma unroll
                    for (int mi = 0; mi < 2; mi++) {
                        mma_bf16(acc[mi][nj*2],     a[mi], bf[0], bf[1]);
                        mma_bf16(acc[mi][nj*2 + 1], a[mi], bf[2], bf[3]);
                    }
                }
            }
        }
        __syncthreads();
    }

    float* op = out + (size_t)bh * SEQ * DKDIM;
    #pragma unroll
    for (int mi = 0; mi < 2; mi++) {
        const int r0 = qBase + wm + mi * 16 + (lane >> 2);
        #pragma unroll
        for (int nj = 0; nj < 4; nj++) {
            const int col = wn + nj * 8 + (lane & 3) * 2;
            float2 w0 = {acc[mi][nj][0], acc[mi][nj][1]};
            float2 w1 = {acc[mi][nj][2], acc[mi][nj][3]};
            *(float2*)&op[(size_t)r0 * DKDIM + col]       = w0;
            *(float2*)&op[(size_t)(r0 + 8) * DKDIM + col] = w1;
        }
    }
}

// ---------------------------------------------------------------------------
extern "C" void kernel_launch(void* const* d_in, const int* in_sizes, int n_in,
                              void* d_out, int out_size)
{
    const float* Q    = (const float*)d_in[0];
    const float* K    = (const float*)d_in[1];
    const float* V    = (const float*)d_in[2];
    const int*   mask = (const int*)  d_in[3];

    float* out  = (float*)d_out;
    float* attn = out + (size_t)BH * SEQ * DKDIM;

    cudaFuncSetAttribute(scores_tc, cudaFuncAttributeMaxDynamicSharedMemorySize, S_SMEM_TOTAL);
    cudaFuncSetAttribute(out_tc,    cudaFuncAttributeMaxDynamicSharedMemorySize, O_SMEM_TOTAL);

    scores_tc<<<dim3(SEQ / 128, SEQ / 128, BH), 256, S_SMEM_TOTAL>>>(Q, K, mask, attn);
    softmax_kernel<<<BH * SEQ, 256>>>(attn);
    out_tc<<<dim3(SEQ / 128, BH), 256, O_SMEM_TOTAL>>>(attn, V, out);
}